// round 1
// baseline (speedup 1.0000x reference)
#include <cuda_runtime.h>
#include <cuda_bf16.h>
#include <cstdint>

// Problem constants
#define BB 2
#define SS 2048
#define EE 1024
#define HH 16
#define DD 64
#define RR 16
#define BH (BB*HH)          // 32
#define NQK (HH*DD)         // 1024
#define NTOT (2*NQK + HH*RR) // 2304
#define MROWS (BB*SS)       // 4096

// ---------------- device scratch ----------------
__device__ float g_Wall[EE * NTOT];          // packed [E][2304]
__device__ float g_ball[NTOT];
__device__ float g_q[BH * SS * DD];          // (b,h,s,d)
__device__ float g_k[BH * SS * DD];
__device__ float g_vd[BH * SS * RR];
__device__ float g_v[BH * SS * DD];

// ---------------- pack weights ----------------
__global__ void pack_kernel(const float* __restrict__ Wq, const float* __restrict__ bq,
                            const float* __restrict__ Wk, const float* __restrict__ bk,
                            const float* __restrict__ Wvd, const float* __restrict__ bvd) {
    int idx = blockIdx.x * blockDim.x + threadIdx.x;
    const int total = EE * NTOT;
    if (idx < total) {
        int e = idx / NTOT;
        int n = idx % NTOT;
        float w;
        if (n < NQK) {
            int h = n >> 6, d = n & 63;
            w = Wq[(h * EE + e) * DD + d];
        } else if (n < 2 * NQK) {
            int nn = n - NQK;
            int h = nn >> 6, d = nn & 63;
            w = Wk[(h * EE + e) * DD + d];
        } else {
            int nn = n - 2 * NQK;
            int h = nn >> 4, r = nn & 15;
            w = Wvd[(h * EE + e) * RR + r];
        }
        g_Wall[idx] = w;
    }
    if (idx < NTOT) {
        float bv;
        if (idx < NQK)          bv = bq[idx];
        else if (idx < 2 * NQK) bv = bk[idx - NQK];
        else                    bv = bvd[idx - 2 * NQK];
        g_ball[idx] = bv;
    }
}

// ---------------- fused QKV projection GEMM ----------------
// C[4096][2304] = X[4096][1024] @ g_Wall + g_ball, scattered to g_q/g_k/g_vd
__global__ void __launch_bounds__(256) qkv_gemm_kernel(const float* __restrict__ X) {
    __shared__ float As[16][68];  // [k][m], padded
    __shared__ float Bs[16][68];  // [k][n], padded

    int m0 = blockIdx.y * 64;
    int n0 = blockIdx.x * 64;
    int tid = threadIdx.x;
    int ty = tid >> 4;        // 0..15 -> m sub
    int tx = tid & 15;        // 0..15 -> n sub

    float c[4][4];
#pragma unroll
    for (int i = 0; i < 4; ++i)
#pragma unroll
        for (int j = 0; j < 4; ++j) c[i][j] = 0.f;

    for (int k0 = 0; k0 < EE; k0 += 16) {
        __syncthreads();
        {
            // A tile: 64 rows x 16 k, transposed into As[k][m]
            int r  = tid >> 2;          // 0..63
            int c4 = (tid & 3) * 4;     // 0,4,8,12
            float4 a = *(const float4*)(X + (size_t)(m0 + r) * EE + k0 + c4);
            As[c4 + 0][r] = a.x;
            As[c4 + 1][r] = a.y;
            As[c4 + 2][r] = a.z;
            As[c4 + 3][r] = a.w;
            // B tile: 16 k x 64 n, natural
            int rb = tid >> 4;          // 0..15
            int cb = (tid & 15) * 4;    // 0..60
            *(float4*)(&Bs[rb][cb]) =
                *(const float4*)(g_Wall + (size_t)(k0 + rb) * NTOT + n0 + cb);
        }
        __syncthreads();
#pragma unroll
        for (int kk = 0; kk < 16; ++kk) {
            float4 a = *(float4*)(&As[kk][ty * 4]);
            float4 b = *(float4*)(&Bs[kk][tx * 4]);
            c[0][0] += a.x * b.x; c[0][1] += a.x * b.y; c[0][2] += a.x * b.z; c[0][3] += a.x * b.w;
            c[1][0] += a.y * b.x; c[1][1] += a.y * b.y; c[1][2] += a.y * b.z; c[1][3] += a.y * b.w;
            c[2][0] += a.z * b.x; c[2][1] += a.z * b.y; c[2][2] += a.z * b.z; c[2][3] += a.z * b.w;
            c[3][0] += a.w * b.x; c[3][1] += a.w * b.y; c[3][2] += a.w * b.z; c[3][3] += a.w * b.w;
        }
    }

    // epilogue: bias + scatter
#pragma unroll
    for (int j = 0; j < 4; ++j) {
        int n = n0 + tx * 4 + j;
        float bias = g_ball[n];
#pragma unroll
        for (int i = 0; i < 4; ++i) {
            int m = m0 + ty * 4 + i;
            int b = m >> 11;          // /2048
            int s = m & 2047;
            float val = c[i][j] + bias;
            if (n < NQK) {
                int h = n >> 6, d = n & 63;
                g_q[(((size_t)(b * HH + h)) * SS + s) * DD + d] = val;
            } else if (n < 2 * NQK) {
                int nn = n - NQK;
                int h = nn >> 6, d = nn & 63;
                g_k[(((size_t)(b * HH + h)) * SS + s) * DD + d] = val;
            } else {
                int nn = n - 2 * NQK;
                int h = nn >> 4, r = nn & 15;
                g_vd[(((size_t)(b * HH + h)) * SS + s) * RR + r] = val;
            }
        }
    }
}

// ---------------- V up-projection: V = Vd @ Wvu + bvu ----------------
__global__ void vu_kernel(const float* __restrict__ Wvu, const float* __restrict__ bvu) {
    int g = blockIdx.x * 4 + threadIdx.y;   // row in [0, BH*SS)
    int d = threadIdx.x;                    // 0..63
    int h = (g >> 11) & 15;                 // (g / SS) % HH
    float acc = bvu[h * DD + d];
    const float* vdrow = g_vd + (size_t)g * RR;
    const float* w = Wvu + (size_t)h * RR * DD;
#pragma unroll
    for (int r = 0; r < RR; ++r) acc += vdrow[r] * w[r * DD + d];
    g_v[(size_t)g * DD + d] = acc;
}

// ---------------- flash attention (reverse-causal) ----------------
// grid: (S/64 qtiles, BH). block: 256 threads (16x16), 4x4 register tile.
__global__ void __launch_bounds__(256) attn_kernel(float* __restrict__ out) {
    extern __shared__ float sm[];
    float* Qt = sm;                 // [64][68]  (d, q)
    float* Kt = Qt + 64 * 68;       // [64][68]  (d, k)
    float* Vs = Kt + 64 * 68;       // [64][68]  (k, d)
    float* Pt = Vs + 64 * 68;       // [64][68]  (k, q)

    const int qt = blockIdx.x;
    const int bh = blockIdx.y;
    const int q0 = qt * 64;
    const float* qb = g_q + (size_t)bh * SS * DD;
    const float* kb = g_k + (size_t)bh * SS * DD;
    const float* vb = g_v + (size_t)bh * SS * DD;

    const int tid = threadIdx.x;
    const int ty = tid >> 4;   // query sub-tile
    const int tx = tid & 15;   // key / d sub-tile

    // load Q tile transposed
#pragma unroll
    for (int it = 0; it < 4; ++it) {
        int idx4 = tid + it * 256;
        int r = idx4 >> 4;            // q local
        int d0 = (idx4 & 15) * 4;
        float4 v4 = *(const float4*)(qb + (size_t)(q0 + r) * DD + d0);
        Qt[(d0 + 0) * 68 + r] = v4.x;
        Qt[(d0 + 1) * 68 + r] = v4.y;
        Qt[(d0 + 2) * 68 + r] = v4.z;
        Qt[(d0 + 3) * 68 + r] = v4.w;
    }

    float o[4][4];
    float m[4], l[4];
#pragma unroll
    for (int i = 0; i < 4; ++i) {
        m[i] = -1e30f; l[i] = 0.f;
#pragma unroll
        for (int j = 0; j < 4; ++j) o[i][j] = 0.f;
    }

    const float scale = 0.03125f;  // 1/sqrt(1024)

    for (int t = qt; t < SS / 64; ++t) {
        __syncthreads();
        // load K (transposed) and V (natural)
#pragma unroll
        for (int it = 0; it < 4; ++it) {
            int idx4 = tid + it * 256;
            int r = idx4 >> 4;
            int d0 = (idx4 & 15) * 4;
            float4 kv = *(const float4*)(kb + (size_t)(t * 64 + r) * DD + d0);
            Kt[(d0 + 0) * 68 + r] = kv.x;
            Kt[(d0 + 1) * 68 + r] = kv.y;
            Kt[(d0 + 2) * 68 + r] = kv.z;
            Kt[(d0 + 3) * 68 + r] = kv.w;
            float4 vv = *(const float4*)(vb + (size_t)(t * 64 + r) * DD + d0);
            *(float4*)(Vs + r * 68 + d0) = vv;
        }
        __syncthreads();

        // S = Q @ K^T
        float s[4][4];
#pragma unroll
        for (int i = 0; i < 4; ++i)
#pragma unroll
            for (int j = 0; j < 4; ++j) s[i][j] = 0.f;
#pragma unroll 8
        for (int d = 0; d < 64; ++d) {
            float4 a = *(float4*)(Qt + d * 68 + ty * 4);
            float4 b = *(float4*)(Kt + d * 68 + tx * 4);
            s[0][0] += a.x * b.x; s[0][1] += a.x * b.y; s[0][2] += a.x * b.z; s[0][3] += a.x * b.w;
            s[1][0] += a.y * b.x; s[1][1] += a.y * b.y; s[1][2] += a.y * b.z; s[1][3] += a.y * b.w;
            s[2][0] += a.z * b.x; s[2][1] += a.z * b.y; s[2][2] += a.z * b.z; s[2][3] += a.z * b.w;
            s[3][0] += a.w * b.x; s[3][1] += a.w * b.y; s[3][2] += a.w * b.z; s[3][3] += a.w * b.w;
        }

        // scale + reverse-causal mask (only diagonal tile can mask)
        if (t == qt) {
#pragma unroll
            for (int i = 0; i < 4; ++i) {
                int qg = q0 + ty * 4 + i;
#pragma unroll
                for (int j = 0; j < 4; ++j) {
                    int kg = t * 64 + tx * 4 + j;
                    s[i][j] = (kg < qg) ? -1e30f : s[i][j] * scale;
                }
            }
        } else {
#pragma unroll
            for (int i = 0; i < 4; ++i)
#pragma unroll
                for (int j = 0; j < 4; ++j) s[i][j] *= scale;
        }

        // online softmax (row reduction across the 16-thread tx group)
#pragma unroll
        for (int i = 0; i < 4; ++i) {
            float rm = fmaxf(fmaxf(s[i][0], s[i][1]), fmaxf(s[i][2], s[i][3]));
#pragma unroll
            for (int off = 8; off; off >>= 1)
                rm = fmaxf(rm, __shfl_xor_sync(0xffffffffu, rm, off, 16));
            float mn = fmaxf(m[i], rm);
            float al = __expf(m[i] - mn);
            float rs = 0.f;
#pragma unroll
            for (int j = 0; j < 4; ++j) {
                float p = __expf(s[i][j] - mn);
                s[i][j] = p;
                rs += p;
            }
#pragma unroll
            for (int off = 8; off; off >>= 1)
                rs += __shfl_xor_sync(0xffffffffu, rs, off, 16);
            l[i] = l[i] * al + rs;
            m[i] = mn;
#pragma unroll
            for (int j = 0; j < 4; ++j) o[i][j] *= al;
        }

        // write P transposed: Pt[k][q]
#pragma unroll
        for (int i = 0; i < 4; ++i)
#pragma unroll
            for (int j = 0; j < 4; ++j)
                Pt[(tx * 4 + j) * 68 + (ty * 4 + i)] = s[i][j];
        __syncthreads();

        // O += P @ V
#pragma unroll 8
        for (int kk = 0; kk < 64; ++kk) {
            float4 a = *(float4*)(Pt + kk * 68 + ty * 4);
            float4 b = *(float4*)(Vs + kk * 68 + tx * 4);
            o[0][0] += a.x * b.x; o[0][1] += a.x * b.y; o[0][2] += a.x * b.z; o[0][3] += a.x * b.w;
            o[1][0] += a.y * b.x; o[1][1] += a.y * b.y; o[1][2] += a.y * b.z; o[1][3] += a.y * b.w;
            o[2][0] += a.z * b.x; o[2][1] += a.z * b.y; o[2][2] += a.z * b.z; o[2][3] += a.z * b.w;
            o[3][0] += a.w * b.x; o[3][1] += a.w * b.y; o[3][2] += a.w * b.z; o[3][3] += a.w * b.w;
        }
    }

    // write normalized output: out[b][s][h*64+d]
    int h = bh % HH, b = bh / HH;
#pragma unroll
    for (int i = 0; i < 4; ++i) {
        int qg = q0 + ty * 4 + i;
        float inv = 1.f / l[i];
#pragma unroll
        for (int j = 0; j < 4; ++j) {
            int d = tx * 4 + j;
            out[(((size_t)(b * SS + qg)) * HH + h) * DD + d] = o[i][j] * inv;
        }
    }
}

// ---------------- launcher ----------------
extern "C" void kernel_launch(void* const* d_in, const int* in_sizes, int n_in,
                              void* d_out, int out_size) {
    const float* x   = (const float*)d_in[0];
    const float* Wq  = (const float*)d_in[1];
    const float* bq  = (const float*)d_in[2];
    const float* Wk  = (const float*)d_in[3];
    const float* bk  = (const float*)d_in[4];
    const float* Wvd = (const float*)d_in[5];
    const float* bvd = (const float*)d_in[6];
    const float* Wvu = (const float*)d_in[7];
    const float* bvu = (const float*)d_in[8];
    float* out = (float*)d_out;

    // 1. pack weights into GEMM-friendly layout
    {
        int total = EE * NTOT;
        pack_kernel<<<(total + 255) / 256, 256>>>(Wq, bq, Wk, bk, Wvd, bvd);
    }
    // 2. fused QKV projection GEMM
    {
        dim3 grid(NTOT / 64, MROWS / 64);  // (36, 64)
        qkv_gemm_kernel<<<grid, 256>>>(x);
    }
    // 3. V up-projection
    {
        dim3 block(64, 4);
        vu_kernel<<<(BH * SS) / 4, block>>>(Wvu, bvu);
    }
    // 4. flash attention
    {
        size_t smem = 4 * 64 * 68 * sizeof(float);  // 69632
        cudaFuncSetAttribute(attn_kernel, cudaFuncAttributeMaxDynamicSharedMemorySize, (int)smem);
        dim3 grid(SS / 64, BH);  // (32, 32)
        attn_kernel<<<grid, 256, smem>>>(out);
    }
}

// round 2
// speedup vs baseline: 1.6819x; 1.6819x over previous
#include <cuda_runtime.h>
#include <cuda_bf16.h>
#include <cstdint>

// Problem constants
#define BB 2
#define SS 2048
#define EE 1024
#define HH 16
#define DD 64
#define RR 16
#define BH (BB*HH)          // 32
#define NQK (HH*DD)         // 1024
#define NTOT (2*NQK + HH*RR) // 2304
#define MROWS (BB*SS)       // 4096

// ---------------- device scratch ----------------
__device__ float g_Wall[EE * NTOT];          // packed [E][2304]
__device__ float g_ball[NTOT];
__device__ float g_q[BH * SS * DD];          // (b,h,s,d)
__device__ float g_k[BH * SS * DD];
__device__ float g_vd[BH * SS * RR];
__device__ float g_v[BH * SS * DD];

// ---------------- pack weights ----------------
__global__ void pack_kernel(const float* __restrict__ Wq, const float* __restrict__ bq,
                            const float* __restrict__ Wk, const float* __restrict__ bk,
                            const float* __restrict__ Wvd, const float* __restrict__ bvd) {
    int idx = blockIdx.x * blockDim.x + threadIdx.x;
    const int total = EE * NTOT;
    if (idx < total) {
        int e = idx / NTOT;
        int n = idx % NTOT;
        float w;
        if (n < NQK) {
            int h = n >> 6, d = n & 63;
            w = Wq[(h * EE + e) * DD + d];
        } else if (n < 2 * NQK) {
            int nn = n - NQK;
            int h = nn >> 6, d = nn & 63;
            w = Wk[(h * EE + e) * DD + d];
        } else {
            int nn = n - 2 * NQK;
            int h = nn >> 4, r = nn & 15;
            w = Wvd[(h * EE + e) * RR + r];
        }
        g_Wall[idx] = w;
    }
    if (idx < NTOT) {
        float bv;
        if (idx < NQK)          bv = bq[idx];
        else if (idx < 2 * NQK) bv = bk[idx - NQK];
        else                    bv = bvd[idx - 2 * NQK];
        g_ball[idx] = bv;
    }
}

// ---------------- fused QKV projection GEMM (fp32, unchanged) ----------------
__global__ void __launch_bounds__(256) qkv_gemm_kernel(const float* __restrict__ X) {
    __shared__ float As[16][68];
    __shared__ float Bs[16][68];

    int m0 = blockIdx.y * 64;
    int n0 = blockIdx.x * 64;
    int tid = threadIdx.x;
    int ty = tid >> 4;
    int tx = tid & 15;

    float c[4][4];
#pragma unroll
    for (int i = 0; i < 4; ++i)
#pragma unroll
        for (int j = 0; j < 4; ++j) c[i][j] = 0.f;

    for (int k0 = 0; k0 < EE; k0 += 16) {
        __syncthreads();
        {
            int r  = tid >> 2;
            int c4 = (tid & 3) * 4;
            float4 a = *(const float4*)(X + (size_t)(m0 + r) * EE + k0 + c4);
            As[c4 + 0][r] = a.x;
            As[c4 + 1][r] = a.y;
            As[c4 + 2][r] = a.z;
            As[c4 + 3][r] = a.w;
            int rb = tid >> 4;
            int cb = (tid & 15) * 4;
            *(float4*)(&Bs[rb][cb]) =
                *(const float4*)(g_Wall + (size_t)(k0 + rb) * NTOT + n0 + cb);
        }
        __syncthreads();
#pragma unroll
        for (int kk = 0; kk < 16; ++kk) {
            float4 a = *(float4*)(&As[kk][ty * 4]);
            float4 b = *(float4*)(&Bs[kk][tx * 4]);
            c[0][0] += a.x * b.x; c[0][1] += a.x * b.y; c[0][2] += a.x * b.z; c[0][3] += a.x * b.w;
            c[1][0] += a.y * b.x; c[1][1] += a.y * b.y; c[1][2] += a.y * b.z; c[1][3] += a.y * b.w;
            c[2][0] += a.z * b.x; c[2][1] += a.z * b.y; c[2][2] += a.z * b.z; c[2][3] += a.z * b.w;
            c[3][0] += a.w * b.x; c[3][1] += a.w * b.y; c[3][2] += a.w * b.z; c[3][3] += a.w * b.w;
        }
    }

#pragma unroll
    for (int j = 0; j < 4; ++j) {
        int n = n0 + tx * 4 + j;
        float bias = g_ball[n];
#pragma unroll
        for (int i = 0; i < 4; ++i) {
            int m = m0 + ty * 4 + i;
            int b = m >> 11;
            int s = m & 2047;
            float val = c[i][j] + bias;
            if (n < NQK) {
                int h = n >> 6, d = n & 63;
                g_q[(((size_t)(b * HH + h)) * SS + s) * DD + d] = val;
            } else if (n < 2 * NQK) {
                int nn = n - NQK;
                int h = nn >> 6, d = nn & 63;
                g_k[(((size_t)(b * HH + h)) * SS + s) * DD + d] = val;
            } else {
                int nn = n - 2 * NQK;
                int h = nn >> 4, r = nn & 15;
                g_vd[(((size_t)(b * HH + h)) * SS + s) * RR + r] = val;
            }
        }
    }
}

// ---------------- V up-projection ----------------
__global__ void vu_kernel(const float* __restrict__ Wvu, const float* __restrict__ bvu) {
    int g = blockIdx.x * 4 + threadIdx.y;
    int d = threadIdx.x;
    int h = (g >> 11) & 15;
    float acc = bvu[h * DD + d];
    const float* vdrow = g_vd + (size_t)g * RR;
    const float* w = Wvu + (size_t)h * RR * DD;
#pragma unroll
    for (int r = 0; r < RR; ++r) acc += vdrow[r] * w[r * DD + d];
    g_v[(size_t)g * DD + d] = acc;
}

// ---------------- tf32 helpers ----------------
__device__ __forceinline__ uint32_t f2tf(float f) {
    uint32_t r;
    asm("cvt.rna.tf32.f32 %0, %1;" : "=r"(r) : "f"(f));
    return r;
}

__device__ __forceinline__ void mma_tf32(float c[4], const uint32_t a[4], uint32_t b0, uint32_t b1) {
    asm volatile(
        "mma.sync.aligned.m16n8k8.row.col.f32.tf32.tf32.f32 "
        "{%0,%1,%2,%3}, {%4,%5,%6,%7}, {%8,%9}, {%0,%1,%2,%3};"
        : "+f"(c[0]), "+f"(c[1]), "+f"(c[2]), "+f"(c[3])
        : "r"(a[0]), "r"(a[1]), "r"(a[2]), "r"(a[3]), "r"(b0), "r"(b1));
}

// ---------------- flash attention: tf32 tensor-core version ----------------
// grid (32 qtiles, 32 bh), 128 threads (4 warps, 16 q-rows each).
#define SMS 68   // smem row stride (floats): (4r + c) mod 32 conflict-free
__global__ void __launch_bounds__(128) attn_kernel(float* __restrict__ out) {
    extern __shared__ uint32_t sm[];
    uint32_t* Ks = sm;                // [64][68]  (key, d)  -- also Q staging
    uint32_t* Vs = sm + 64 * SMS;     // [64][68]  (key, d)

    const int qt = blockIdx.x;
    const int bh = blockIdx.y;
    const int q0 = qt * 64;
    const float* qb = g_q + (size_t)bh * SS * DD;
    const float* kb = g_k + (size_t)bh * SS * DD;
    const float* vb = g_v + (size_t)bh * SS * DD;

    const int tid = threadIdx.x;
    const int lane = tid & 31;
    const int warp = tid >> 5;
    const int lg = lane >> 2;   // group id 0..7
    const int lr = lane & 3;    // id in group 0..3

    const float scale = 0.03125f;  // 1/sqrt(1024)

    // ---- stage Q into Ks buffer (scaled + tf32), then pull fragments ----
#pragma unroll
    for (int it = 0; it < 8; ++it) {
        int idx4 = tid + it * 128;       // 1024 float4 slots
        int r = idx4 >> 4;
        int c4 = (idx4 & 15) * 4;
        float4 v4 = *(const float4*)(qb + (size_t)(q0 + r) * DD + c4);
        uint4 u;
        u.x = f2tf(v4.x * scale); u.y = f2tf(v4.y * scale);
        u.z = f2tf(v4.z * scale); u.w = f2tf(v4.w * scale);
        *(uint4*)(Ks + r * SMS + c4) = u;
    }
    __syncthreads();

    uint32_t aq[8][4];
    {
        int row = warp * 16 + lg;
#pragma unroll
        for (int kc = 0; kc < 8; ++kc) {
            aq[kc][0] = Ks[row * SMS + kc * 8 + lr];
            aq[kc][1] = Ks[(row + 8) * SMS + kc * 8 + lr];
            aq[kc][2] = Ks[row * SMS + kc * 8 + lr + 4];
            aq[kc][3] = Ks[(row + 8) * SMS + kc * 8 + lr + 4];
        }
    }

    float o[8][4];
    float m0r = -1e30f, m1r = -1e30f, l0r = 0.f, l1r = 0.f;
#pragma unroll
    for (int j = 0; j < 8; ++j)
#pragma unroll
        for (int e = 0; e < 4; ++e) o[j][e] = 0.f;

    for (int t = qt; t < SS / 64; ++t) {
        __syncthreads();   // protect Ks (Q frags done / prev iter reads done)
        // stage K and V tiles (tf32)
#pragma unroll
        for (int it = 0; it < 8; ++it) {
            int idx4 = tid + it * 128;
            int r = idx4 >> 4;
            int c4 = (idx4 & 15) * 4;
            float4 kv = *(const float4*)(kb + (size_t)(t * 64 + r) * DD + c4);
            uint4 uk;
            uk.x = f2tf(kv.x); uk.y = f2tf(kv.y); uk.z = f2tf(kv.z); uk.w = f2tf(kv.w);
            *(uint4*)(Ks + r * SMS + c4) = uk;
            float4 vv = *(const float4*)(vb + (size_t)(t * 64 + r) * DD + c4);
            uint4 uv;
            uv.x = f2tf(vv.x); uv.y = f2tf(vv.y); uv.z = f2tf(vv.z); uv.w = f2tf(vv.w);
            *(uint4*)(Vs + r * SMS + c4) = uv;
        }
        __syncthreads();

        // ---- S = Q @ K^T ----
        float s[8][4];
#pragma unroll
        for (int j = 0; j < 8; ++j)
#pragma unroll
            for (int e = 0; e < 4; ++e) s[j][e] = 0.f;

#pragma unroll
        for (int j = 0; j < 8; ++j) {
#pragma unroll
            for (int kc = 0; kc < 8; ++kc) {
                uint32_t b0 = Ks[(j * 8 + lg) * SMS + kc * 8 + lr];
                uint32_t b1 = Ks[(j * 8 + lg) * SMS + kc * 8 + lr + 4];
                mma_tf32(s[j], aq[kc], b0, b1);
            }
        }

        // ---- mask (diagonal tile only): key < query -> -inf ----
        if (t == qt) {
            int qr0 = q0 + warp * 16 + lg;
#pragma unroll
            for (int j = 0; j < 8; ++j) {
                int kg = t * 64 + j * 8 + lr * 2;
                if (kg < qr0)          s[j][0] = -1e30f;
                if (kg + 1 < qr0)      s[j][1] = -1e30f;
                if (kg < qr0 + 8)      s[j][2] = -1e30f;
                if (kg + 1 < qr0 + 8)  s[j][3] = -1e30f;
            }
        }

        // ---- online softmax over fragment rows ----
        float rm0 = -1e30f, rm1 = -1e30f;
#pragma unroll
        for (int j = 0; j < 8; ++j) {
            rm0 = fmaxf(rm0, fmaxf(s[j][0], s[j][1]));
            rm1 = fmaxf(rm1, fmaxf(s[j][2], s[j][3]));
        }
        rm0 = fmaxf(rm0, __shfl_xor_sync(0xffffffffu, rm0, 1));
        rm0 = fmaxf(rm0, __shfl_xor_sync(0xffffffffu, rm0, 2));
        rm1 = fmaxf(rm1, __shfl_xor_sync(0xffffffffu, rm1, 1));
        rm1 = fmaxf(rm1, __shfl_xor_sync(0xffffffffu, rm1, 2));

        float mn0 = fmaxf(m0r, rm0);
        float mn1 = fmaxf(m1r, rm1);
        float al0 = __expf(m0r - mn0);
        float al1 = __expf(m1r - mn1);
        m0r = mn0; m1r = mn1;

        float rs0 = 0.f, rs1 = 0.f;
        uint32_t p[8][4];
#pragma unroll
        for (int j = 0; j < 8; ++j) {
            float p0 = __expf(s[j][0] - mn0);
            float p1 = __expf(s[j][1] - mn0);
            float p2 = __expf(s[j][2] - mn1);
            float p3 = __expf(s[j][3] - mn1);
            rs0 += p0 + p1;
            rs1 += p2 + p3;
            p[j][0] = f2tf(p0); p[j][1] = f2tf(p1);
            p[j][2] = f2tf(p2); p[j][3] = f2tf(p3);
        }
        rs0 += __shfl_xor_sync(0xffffffffu, rs0, 1);
        rs0 += __shfl_xor_sync(0xffffffffu, rs0, 2);
        rs1 += __shfl_xor_sync(0xffffffffu, rs1, 1);
        rs1 += __shfl_xor_sync(0xffffffffu, rs1, 2);
        l0r = l0r * al0 + rs0;
        l1r = l1r * al1 + rs1;

#pragma unroll
        for (int j = 0; j < 8; ++j) {
            o[j][0] *= al0; o[j][1] *= al0;
            o[j][2] *= al1; o[j][3] *= al1;
        }

        // ---- O += P @ V  (P fed directly from C-fragments via V row permutation) ----
        // mma slot kk maps to key 2*(kk%4)+(kk>=4); a = {c0, c2, c1, c3}
#pragma unroll
        for (int g = 0; g < 8; ++g) {
            uint32_t ap[4];
            ap[0] = p[g][0]; ap[1] = p[g][2]; ap[2] = p[g][1]; ap[3] = p[g][3];
#pragma unroll
            for (int j2 = 0; j2 < 8; ++j2) {
                uint32_t b0 = Vs[(g * 8 + 2 * lr) * SMS + j2 * 8 + lg];
                uint32_t b1 = Vs[(g * 8 + 2 * lr + 1) * SMS + j2 * 8 + lg];
                mma_tf32(o[j2], ap, b0, b1);
            }
        }
    }

    // ---- write normalized output: out[b][s][h*64+d] ----
    int h = bh % HH, b = bh / HH;
    float inv0 = 1.f / l0r;
    float inv1 = 1.f / l1r;
    int qr0 = q0 + warp * 16 + lg;
#pragma unroll
    for (int j2 = 0; j2 < 8; ++j2) {
        int d = j2 * 8 + lr * 2;
        float2 v0 = make_float2(o[j2][0] * inv0, o[j2][1] * inv0);
        float2 v1 = make_float2(o[j2][2] * inv1, o[j2][3] * inv1);
        *(float2*)(out + (((size_t)(b * SS + qr0)) * HH + h) * DD + d) = v0;
        *(float2*)(out + (((size_t)(b * SS + qr0 + 8)) * HH + h) * DD + d) = v1;
    }
}

// ---------------- launcher ----------------
extern "C" void kernel_launch(void* const* d_in, const int* in_sizes, int n_in,
                              void* d_out, int out_size) {
    const float* x   = (const float*)d_in[0];
    const float* Wq  = (const float*)d_in[1];
    const float* bq  = (const float*)d_in[2];
    const float* Wk  = (const float*)d_in[3];
    const float* bk  = (const float*)d_in[4];
    const float* Wvd = (const float*)d_in[5];
    const float* bvd = (const float*)d_in[6];
    const float* Wvu = (const float*)d_in[7];
    const float* bvu = (const float*)d_in[8];
    float* out = (float*)d_out;

    {
        int total = EE * NTOT;
        pack_kernel<<<(total + 255) / 256, 256>>>(Wq, bq, Wk, bk, Wvd, bvd);
    }
    {
        dim3 grid(NTOT / 64, MROWS / 64);
        qkv_gemm_kernel<<<grid, 256>>>(x);
    }
    {
        dim3 block(64, 4);
        vu_kernel<<<(BH * SS) / 4, block>>>(Wvu, bvu);
    }
    {
        size_t smem = 2 * 64 * SMS * sizeof(float);  // 34816 bytes
        cudaFuncSetAttribute(attn_kernel, cudaFuncAttributeMaxDynamicSharedMemorySize, (int)smem);
        dim3 grid(SS / 64, BH);
        attn_kernel<<<grid, 128, smem>>>(out);
    }
}

// round 3
// speedup vs baseline: 3.1482x; 1.8718x over previous
#include <cuda_runtime.h>
#include <cuda_bf16.h>
#include <cstdint>

// Problem constants
#define BB 2
#define SS 2048
#define EE 1024
#define HH 16
#define DD 64
#define RR 16
#define BH (BB*HH)          // 32
#define NQK (HH*DD)         // 1024
#define NTOT (2*NQK + HH*RR) // 2304
#define MROWS (BB*SS)       // 4096

// ---------------- device scratch ----------------
__device__ float g_Wall[EE * NTOT];          // packed [E][2304]
__device__ float g_ball[NTOT];
__device__ float g_q[BH * SS * DD];          // (b,h,s,d)
__device__ float g_k[BH * SS * DD];
__device__ float g_vd[BH * SS * RR];
__device__ float g_v[BH * SS * DD];

// ---------------- pack weights ----------------
__global__ void pack_kernel(const float* __restrict__ Wq, const float* __restrict__ bq,
                            const float* __restrict__ Wk, const float* __restrict__ bk,
                            const float* __restrict__ Wvd, const float* __restrict__ bvd) {
    int idx = blockIdx.x * blockDim.x + threadIdx.x;
    const int total = EE * NTOT;
    if (idx < total) {
        int e = idx / NTOT;
        int n = idx % NTOT;
        float w;
        if (n < NQK) {
            int h = n >> 6, d = n & 63;
            w = Wq[(h * EE + e) * DD + d];
        } else if (n < 2 * NQK) {
            int nn = n - NQK;
            int h = nn >> 6, d = nn & 63;
            w = Wk[(h * EE + e) * DD + d];
        } else {
            int nn = n - 2 * NQK;
            int h = nn >> 4, r = nn & 15;
            w = Wvd[(h * EE + e) * RR + r];
        }
        g_Wall[idx] = w;
    }
    if (idx < NTOT) {
        float bv;
        if (idx < NQK)          bv = bq[idx];
        else if (idx < 2 * NQK) bv = bk[idx - NQK];
        else                    bv = bvd[idx - 2 * NQK];
        g_ball[idx] = bv;
    }
}

// ---------------- tf32 helpers ----------------
__device__ __forceinline__ uint32_t f2tf(float f) {
    uint32_t r;
    asm("cvt.rna.tf32.f32 %0, %1;" : "=r"(r) : "f"(f));
    return r;
}

__device__ __forceinline__ void mma_tf32(float c[4], const uint32_t a[4], uint32_t b0, uint32_t b1) {
    asm volatile(
        "mma.sync.aligned.m16n8k8.row.col.f32.tf32.tf32.f32 "
        "{%0,%1,%2,%3}, {%4,%5,%6,%7}, {%8,%9}, {%0,%1,%2,%3};"
        : "+f"(c[0]), "+f"(c[1]), "+f"(c[2]), "+f"(c[3])
        : "r"(a[0]), "r"(a[1]), "r"(a[2]), "r"(a[3]), "r"(b0), "r"(b1));
}

// ---------------- fused QKV projection GEMM (tf32 tensor cores) ----------------
// C[4096][2304] = X @ g_Wall + g_ball -> scatter to g_q/g_k/g_vd
// Block 128x128x16, 256 threads (8 warps, 2x4), warp tile 64x32.
#define ASTR 20
#define BSTR 136
__global__ void __launch_bounds__(256) qkv_gemm_kernel(const float* __restrict__ X) {
    __shared__ uint32_t As[2][128 * ASTR];   // [m][k] tf32
    __shared__ uint32_t Bs[2][16 * BSTR];    // [k][n] tf32

    const int m0 = blockIdx.y * 128;
    const int n0 = blockIdx.x * 128;
    const int tid = threadIdx.x;
    const int lane = tid & 31;
    const int warp = tid >> 5;
    const int lg = lane >> 2;      // 0..7
    const int lr = lane & 3;       // 0..3
    const int wm = (warp >> 2) * 64;   // warp m offset
    const int wn = (warp & 3) * 32;    // warp n offset

    // per-thread global load coords
    const int am = tid >> 1;                 // 0..127  (A row)
    const int ac = (tid & 1) * 8;            // 0 or 8  (A col base; 2 float4 each)
    const int bk = tid >> 4;                 // 0..15   (B row)
    const int bc = (tid & 15) * 8;           // 0..120  (B col base; 2 float4 each)

    float c[4][4][4];
#pragma unroll
    for (int i = 0; i < 4; ++i)
#pragma unroll
        for (int j = 0; j < 4; ++j)
#pragma unroll
            for (int e = 0; e < 4; ++e) c[i][j][e] = 0.f;

    float4 pa0, pa1, pb0, pb1;

    // prologue: prefetch k-tile 0
    pa0 = *(const float4*)(X + (size_t)(m0 + am) * EE + ac);
    pa1 = *(const float4*)(X + (size_t)(m0 + am) * EE + ac + 4);
    pb0 = *(const float4*)(g_Wall + (size_t)bk * NTOT + n0 + bc);
    pb1 = *(const float4*)(g_Wall + (size_t)bk * NTOT + n0 + bc + 4);
    {
        uint4 u0 = make_uint4(f2tf(pa0.x), f2tf(pa0.y), f2tf(pa0.z), f2tf(pa0.w));
        uint4 u1 = make_uint4(f2tf(pa1.x), f2tf(pa1.y), f2tf(pa1.z), f2tf(pa1.w));
        *(uint4*)(&As[0][am * ASTR + ac])     = u0;
        *(uint4*)(&As[0][am * ASTR + ac + 4]) = u1;
        uint4 v0 = make_uint4(f2tf(pb0.x), f2tf(pb0.y), f2tf(pb0.z), f2tf(pb0.w));
        uint4 v1 = make_uint4(f2tf(pb1.x), f2tf(pb1.y), f2tf(pb1.z), f2tf(pb1.w));
        *(uint4*)(&Bs[0][bk * BSTR + bc])     = v0;
        *(uint4*)(&Bs[0][bk * BSTR + bc + 4]) = v1;
    }
    __syncthreads();

    const int NK = EE / 16;   // 64
    for (int kt = 0; kt < NK; ++kt) {
        const int cur = kt & 1;
        if (kt + 1 < NK) {
            int k0 = (kt + 1) * 16;
            pa0 = *(const float4*)(X + (size_t)(m0 + am) * EE + k0 + ac);
            pa1 = *(const float4*)(X + (size_t)(m0 + am) * EE + k0 + ac + 4);
            pb0 = *(const float4*)(g_Wall + (size_t)(k0 + bk) * NTOT + n0 + bc);
            pb1 = *(const float4*)(g_Wall + (size_t)(k0 + bk) * NTOT + n0 + bc + 4);
        }

#pragma unroll
        for (int kk = 0; kk < 2; ++kk) {
            uint32_t a[4][4];
#pragma unroll
            for (int mt = 0; mt < 4; ++mt) {
                int row = wm + mt * 16;
                a[mt][0] = As[cur][(row + lg) * ASTR + kk * 8 + lr];
                a[mt][1] = As[cur][(row + lg + 8) * ASTR + kk * 8 + lr];
                a[mt][2] = As[cur][(row + lg) * ASTR + kk * 8 + lr + 4];
                a[mt][3] = As[cur][(row + lg + 8) * ASTR + kk * 8 + lr + 4];
            }
            uint32_t b[4][2];
#pragma unroll
            for (int nt = 0; nt < 4; ++nt) {
                int col = wn + nt * 8 + lg;
                b[nt][0] = Bs[cur][(kk * 8 + lr) * BSTR + col];
                b[nt][1] = Bs[cur][(kk * 8 + lr + 4) * BSTR + col];
            }
#pragma unroll
            for (int mt = 0; mt < 4; ++mt)
#pragma unroll
                for (int nt = 0; nt < 4; ++nt)
                    mma_tf32(c[mt][nt], a[mt], b[nt][0], b[nt][1]);
        }

        if (kt + 1 < NK) {
            int nxt = cur ^ 1;
            uint4 u0 = make_uint4(f2tf(pa0.x), f2tf(pa0.y), f2tf(pa0.z), f2tf(pa0.w));
            uint4 u1 = make_uint4(f2tf(pa1.x), f2tf(pa1.y), f2tf(pa1.z), f2tf(pa1.w));
            *(uint4*)(&As[nxt][am * ASTR + ac])     = u0;
            *(uint4*)(&As[nxt][am * ASTR + ac + 4]) = u1;
            uint4 v0 = make_uint4(f2tf(pb0.x), f2tf(pb0.y), f2tf(pb0.z), f2tf(pb0.w));
            uint4 v1 = make_uint4(f2tf(pb1.x), f2tf(pb1.y), f2tf(pb1.z), f2tf(pb1.w));
            *(uint4*)(&Bs[nxt][bk * BSTR + bc])     = v0;
            *(uint4*)(&Bs[nxt][bk * BSTR + bc + 4]) = v1;
        }
        __syncthreads();
    }

    // epilogue: bias + scatter (float2 along n)
#pragma unroll
    for (int mt = 0; mt < 4; ++mt) {
#pragma unroll
        for (int e2 = 0; e2 < 2; ++e2) {   // 0: rows lg, 1: rows lg+8
            int m = m0 + wm + mt * 16 + lg + e2 * 8;
            int b = m >> 11;
            int s = m & 2047;
#pragma unroll
            for (int nt = 0; nt < 4; ++nt) {
                int n = n0 + wn + nt * 8 + 2 * lr;
                float2 bias = *(const float2*)(g_ball + n);
                float2 val;
                val.x = c[mt][nt][e2 * 2 + 0] + bias.x;
                val.y = c[mt][nt][e2 * 2 + 1] + bias.y;
                if (n < NQK) {
                    int h = n >> 6, d = n & 63;
                    *(float2*)(g_q + (((size_t)(b * HH + h)) * SS + s) * DD + d) = val;
                } else if (n < 2 * NQK) {
                    int nn = n - NQK;
                    int h = nn >> 6, d = nn & 63;
                    *(float2*)(g_k + (((size_t)(b * HH + h)) * SS + s) * DD + d) = val;
                } else {
                    int nn = n - 2 * NQK;
                    int h = nn >> 4, r = nn & 15;
                    *(float2*)(g_vd + (((size_t)(b * HH + h)) * SS + s) * RR + r) = val;
                }
            }
        }
    }
}

// ---------------- V up-projection ----------------
__global__ void vu_kernel(const float* __restrict__ Wvu, const float* __restrict__ bvu) {
    int g = blockIdx.x * 4 + threadIdx.y;
    int d = threadIdx.x;
    int h = (g >> 11) & 15;
    float acc = bvu[h * DD + d];
    const float* vdrow = g_vd + (size_t)g * RR;
    const float* w = Wvu + (size_t)h * RR * DD;
#pragma unroll
    for (int r = 0; r < RR; ++r) acc += vdrow[r] * w[r * DD + d];
    g_v[(size_t)g * DD + d] = acc;
}

// ---------------- flash attention: tf32 tensor-core version ----------------
#define SMS 68
__global__ void __launch_bounds__(128) attn_kernel(float* __restrict__ out) {
    extern __shared__ uint32_t sm[];
    uint32_t* Ks = sm;                // [64][68]
    uint32_t* Vs = sm + 64 * SMS;     // [64][68]

    const int qt = blockIdx.x;
    const int bh = blockIdx.y;
    const int q0 = qt * 64;
    const float* qb = g_q + (size_t)bh * SS * DD;
    const float* kb = g_k + (size_t)bh * SS * DD;
    const float* vb = g_v + (size_t)bh * SS * DD;

    const int tid = threadIdx.x;
    const int lane = tid & 31;
    const int warp = tid >> 5;
    const int lg = lane >> 2;
    const int lr = lane & 3;

    const float scale = 0.03125f;

#pragma unroll
    for (int it = 0; it < 8; ++it) {
        int idx4 = tid + it * 128;
        int r = idx4 >> 4;
        int c4 = (idx4 & 15) * 4;
        float4 v4 = *(const float4*)(qb + (size_t)(q0 + r) * DD + c4);
        uint4 u;
        u.x = f2tf(v4.x * scale); u.y = f2tf(v4.y * scale);
        u.z = f2tf(v4.z * scale); u.w = f2tf(v4.w * scale);
        *(uint4*)(Ks + r * SMS + c4) = u;
    }
    __syncthreads();

    uint32_t aq[8][4];
    {
        int row = warp * 16 + lg;
#pragma unroll
        for (int kc = 0; kc < 8; ++kc) {
            aq[kc][0] = Ks[row * SMS + kc * 8 + lr];
            aq[kc][1] = Ks[(row + 8) * SMS + kc * 8 + lr];
            aq[kc][2] = Ks[row * SMS + kc * 8 + lr + 4];
            aq[kc][3] = Ks[(row + 8) * SMS + kc * 8 + lr + 4];
        }
    }

    float o[8][4];
    float m0r = -1e30f, m1r = -1e30f, l0r = 0.f, l1r = 0.f;
#pragma unroll
    for (int j = 0; j < 8; ++j)
#pragma unroll
        for (int e = 0; e < 4; ++e) o[j][e] = 0.f;

    for (int t = qt; t < SS / 64; ++t) {
        __syncthreads();
#pragma unroll
        for (int it = 0; it < 8; ++it) {
            int idx4 = tid + it * 128;
            int r = idx4 >> 4;
            int c4 = (idx4 & 15) * 4;
            float4 kv = *(const float4*)(kb + (size_t)(t * 64 + r) * DD + c4);
            uint4 uk;
            uk.x = f2tf(kv.x); uk.y = f2tf(kv.y); uk.z = f2tf(kv.z); uk.w = f2tf(kv.w);
            *(uint4*)(Ks + r * SMS + c4) = uk;
            float4 vv = *(const float4*)(vb + (size_t)(t * 64 + r) * DD + c4);
            uint4 uv;
            uv.x = f2tf(vv.x); uv.y = f2tf(vv.y); uv.z = f2tf(vv.z); uv.w = f2tf(vv.w);
            *(uint4*)(Vs + r * SMS + c4) = uv;
        }
        __syncthreads();

        float s[8][4];
#pragma unroll
        for (int j = 0; j < 8; ++j)
#pragma unroll
            for (int e = 0; e < 4; ++e) s[j][e] = 0.f;

#pragma unroll
        for (int j = 0; j < 8; ++j) {
#pragma unroll
            for (int kc = 0; kc < 8; ++kc) {
                uint32_t b0 = Ks[(j * 8 + lg) * SMS + kc * 8 + lr];
                uint32_t b1 = Ks[(j * 8 + lg) * SMS + kc * 8 + lr + 4];
                mma_tf32(s[j], aq[kc], b0, b1);
            }
        }

        if (t == qt) {
            int qr0 = q0 + warp * 16 + lg;
#pragma unroll
            for (int j = 0; j < 8; ++j) {
                int kg = t * 64 + j * 8 + lr * 2;
                if (kg < qr0)          s[j][0] = -1e30f;
                if (kg + 1 < qr0)      s[j][1] = -1e30f;
                if (kg < qr0 + 8)      s[j][2] = -1e30f;
                if (kg + 1 < qr0 + 8)  s[j][3] = -1e30f;
            }
        }

        float rm0 = -1e30f, rm1 = -1e30f;
#pragma unroll
        for (int j = 0; j < 8; ++j) {
            rm0 = fmaxf(rm0, fmaxf(s[j][0], s[j][1]));
            rm1 = fmaxf(rm1, fmaxf(s[j][2], s[j][3]));
        }
        rm0 = fmaxf(rm0, __shfl_xor_sync(0xffffffffu, rm0, 1));
        rm0 = fmaxf(rm0, __shfl_xor_sync(0xffffffffu, rm0, 2));
        rm1 = fmaxf(rm1, __shfl_xor_sync(0xffffffffu, rm1, 1));
        rm1 = fmaxf(rm1, __shfl_xor_sync(0xffffffffu, rm1, 2));

        float mn0 = fmaxf(m0r, rm0);
        float mn1 = fmaxf(m1r, rm1);
        float al0 = __expf(m0r - mn0);
        float al1 = __expf(m1r - mn1);
        m0r = mn0; m1r = mn1;

        float rs0 = 0.f, rs1 = 0.f;
        uint32_t p[8][4];
#pragma unroll
        for (int j = 0; j < 8; ++j) {
            float p0 = __expf(s[j][0] - mn0);
            float p1 = __expf(s[j][1] - mn0);
            float p2 = __expf(s[j][2] - mn1);
            float p3 = __expf(s[j][3] - mn1);
            rs0 += p0 + p1;
            rs1 += p2 + p3;
            p[j][0] = f2tf(p0); p[j][1] = f2tf(p1);
            p[j][2] = f2tf(p2); p[j][3] = f2tf(p3);
        }
        rs0 += __shfl_xor_sync(0xffffffffu, rs0, 1);
        rs0 += __shfl_xor_sync(0xffffffffu, rs0, 2);
        rs1 += __shfl_xor_sync(0xffffffffu, rs1, 1);
        rs1 += __shfl_xor_sync(0xffffffffu, rs1, 2);
        l0r = l0r * al0 + rs0;
        l1r = l1r * al1 + rs1;

#pragma unroll
        for (int j = 0; j < 8; ++j) {
            o[j][0] *= al0; o[j][1] *= al0;
            o[j][2] *= al1; o[j][3] *= al1;
        }

#pragma unroll
        for (int g = 0; g < 8; ++g) {
            uint32_t ap[4];
            ap[0] = p[g][0]; ap[1] = p[g][2]; ap[2] = p[g][1]; ap[3] = p[g][3];
#pragma unroll
            for (int j2 = 0; j2 < 8; ++j2) {
                uint32_t b0 = Vs[(g * 8 + 2 * lr) * SMS + j2 * 8 + lg];
                uint32_t b1 = Vs[(g * 8 + 2 * lr + 1) * SMS + j2 * 8 + lg];
                mma_tf32(o[j2], ap, b0, b1);
            }
        }
    }

    int h = bh % HH, b = bh / HH;
    float inv0 = 1.f / l0r;
    float inv1 = 1.f / l1r;
    int qr0 = q0 + warp * 16 + lg;
#pragma unroll
    for (int j2 = 0; j2 < 8; ++j2) {
        int d = j2 * 8 + lr * 2;
        float2 v0 = make_float2(o[j2][0] * inv0, o[j2][1] * inv0);
        float2 v1 = make_float2(o[j2][2] * inv1, o[j2][3] * inv1);
        *(float2*)(out + (((size_t)(b * SS + qr0)) * HH + h) * DD + d) = v0;
        *(float2*)(out + (((size_t)(b * SS + qr0 + 8)) * HH + h) * DD + d) = v1;
    }
}

// ---------------- launcher ----------------
extern "C" void kernel_launch(void* const* d_in, const int* in_sizes, int n_in,
                              void* d_out, int out_size) {
    const float* x   = (const float*)d_in[0];
    const float* Wq  = (const float*)d_in[1];
    const float* bq  = (const float*)d_in[2];
    const float* Wk  = (const float*)d_in[3];
    const float* bk  = (const float*)d_in[4];
    const float* Wvd = (const float*)d_in[5];
    const float* bvd = (const float*)d_in[6];
    const float* Wvu = (const float*)d_in[7];
    const float* bvu = (const float*)d_in[8];
    float* out = (float*)d_out;

    {
        int total = EE * NTOT;
        pack_kernel<<<(total + 255) / 256, 256>>>(Wq, bq, Wk, bk, Wvd, bvd);
    }
    {
        dim3 grid(NTOT / 128, MROWS / 128);  // (18, 32)
        qkv_gemm_kernel<<<grid, 256>>>(x);
    }
    {
        dim3 block(64, 4);
        vu_kernel<<<(BH * SS) / 4, block>>>(Wvu, bvu);
    }
    {
        size_t smem = 2 * 64 * SMS * sizeof(float);
        cudaFuncSetAttribute(attn_kernel, cudaFuncAttributeMaxDynamicSharedMemorySize, (int)smem);
        dim3 grid(SS / 64, BH);
        attn_kernel<<<grid, 128, smem>>>(out);
    }
}